// round 10
// baseline (speedup 1.0000x reference)
#include <cuda_runtime.h>

// QuantumAutoencoder strip-pool + cos. In: [32768,3,32,32] f32 -> Out: [32768,64] f32.
// Terminal config: flat grid, 2 imgs/block, 256 thr, regs ~32, streaming hints.
// float4-slot t (0..255) is the same spatial position across the 3 channels
// (offsets t, t+256, t+512 in float4 units); warp loads are 512B contiguous.
// Patch p = slots 4p..4p+3 -> 2-step shfl_xor reduce; results for 4 patches are
// gathered to lane t%16==0 and stored as one STG.128 (vectorized epilogue).
// Measured at the B300 LTS path-independent throughput cap (~6.7 TB/s).

#define PI_F 3.14159265358979323846f
#define IMGS_PER_BLOCK 2

__global__ void __launch_bounds__(256) qae_kernel(const float4* __restrict__ in,
                                                  float4* __restrict__ out) {
    int t = threadIdx.x;                       // 0..255
    int img0 = blockIdx.x * IMGS_PER_BLOCK;

    float s[IMGS_PER_BLOCK];
    #pragma unroll
    for (int i = 0; i < IMGS_PER_BLOCK; ++i) {
        const float4* p = in + (size_t)(img0 + i) * 768;  // 3*1024/4
        float4 a = __ldcs(p + t);
        float4 b = __ldcs(p + t + 256);
        float4 c = __ldcs(p + t + 512);
        s[i] = ((a.x + a.y) + (a.z + a.w))
             + ((b.x + b.y) + (b.z + b.w))
             + ((c.x + c.y) + (c.z + c.w));
    }

    #pragma unroll
    for (int i = 0; i < IMGS_PER_BLOCK; ++i) {
        // 4-lane sum -> every lane in the group holds the patch total
        float v = s[i];
        v += __shfl_xor_sync(0xffffffffu, v, 1);
        v += __shfl_xor_sync(0xffffffffu, v, 2);
        float mean = v * (1.0f / 48.0f);
        float r = cosf(mean * (PI_F / 255.0f) - (PI_F * 0.5f));
        // gather 4 patch results (groups 4k..4k+3) into lane t%16==0 as float4
        float r1 = __shfl_xor_sync(0xffffffffu, r, 4);   // neighbor patch (xor bit2)
        float r2 = __shfl_xor_sync(0xffffffffu, r, 8);   // xor bit3
        float r3 = __shfl_xor_sync(0xffffffffu, r1, 8);
        if ((t & 15) == 0) {
            float4 o;
            o.x = r;  o.y = r1;  o.z = r2;  o.w = r3;
            __stcs(&out[(size_t)(img0 + i) * 16 + (t >> 4)], o);
        }
    }
}

extern "C" void kernel_launch(void* const* d_in, const int* in_sizes, int n_in,
                              void* d_out, int out_size) {
    const float4* in = (const float4*)d_in[0];
    float4* out = (float4*)d_out;
    int n_img = in_sizes[0] / (3 * 32 * 32);     // 32768
    int blocks = n_img / IMGS_PER_BLOCK;         // 16384
    qae_kernel<<<blocks, 256>>>(in, out);
}

// round 11
// speedup vs baseline: 1.0041x; 1.0041x over previous
#include <cuda_runtime.h>

// QuantumAutoencoder strip-pool + cos. In: [32768,3,32,32] f32 -> Out: [32768,64] f32.
// TERMINAL kernel: flat grid, 2 imgs/block, 256 thr, regs 32, streaming hints.
//
// Layout insight: reference's reshape(B,3,8,8,4,4).mean((-1,-2)) pools 16
// CONTIGUOUS floats per patch (strip pooling). float4-slot t (0..255) is the
// same spatial position across the 3 channels (offsets t, t+256, t+512 in
// float4 units), so each thread directly accumulates its 3-channel partial;
// warp loads are 512B fully-contiguous. Patch p = slots 4p..4p+3 -> 2-step
// shfl_xor reduce; lane (t&3)==0 stores (8 consecutive floats per warp).
//
// Perf status: DRAM 84.6-85.3% across configs, HBM ~6.7 TB/s = B300's
// path-independent LTS cap (~6300 B/cyc). Kernel time ~61.1us vs 60.7us
// traffic floor (<1% gap). MLP-12 (occupancy loss), persistent grid
// (loop-carried MLP collapse), 512-thr blocks and vector-store epilogue
// (neutral) all explored and rejected.

#define PI_F 3.14159265358979323846f
#define IMGS_PER_BLOCK 2

__global__ void __launch_bounds__(256) qae_kernel(const float4* __restrict__ in,
                                                  float* __restrict__ out) {
    int t = threadIdx.x;                       // 0..255
    int img0 = blockIdx.x * IMGS_PER_BLOCK;

    float s[IMGS_PER_BLOCK];
    #pragma unroll
    for (int i = 0; i < IMGS_PER_BLOCK; ++i) {
        const float4* p = in + (size_t)(img0 + i) * 768;  // 3*1024/4
        float4 a = __ldcs(p + t);
        float4 b = __ldcs(p + t + 256);
        float4 c = __ldcs(p + t + 512);
        s[i] = ((a.x + a.y) + (a.z + a.w))
             + ((b.x + b.y) + (b.z + b.w))
             + ((c.x + c.y) + (c.z + c.w));
    }

    #pragma unroll
    for (int i = 0; i < IMGS_PER_BLOCK; ++i) {
        float v = s[i];
        v += __shfl_xor_sync(0xffffffffu, v, 1);
        v += __shfl_xor_sync(0xffffffffu, v, 2);
        if ((t & 3) == 0) {
            float mean = v * (1.0f / 48.0f);
            float ang = mean * (PI_F / 255.0f) - (PI_F * 0.5f);
            __stcs(&out[(size_t)(img0 + i) * 64 + (t >> 2)], cosf(ang));
        }
    }
}

extern "C" void kernel_launch(void* const* d_in, const int* in_sizes, int n_in,
                              void* d_out, int out_size) {
    const float4* in = (const float4*)d_in[0];
    float* out = (float*)d_out;
    int n_img = in_sizes[0] / (3 * 32 * 32);     // 32768
    int blocks = n_img / IMGS_PER_BLOCK;         // 16384
    qae_kernel<<<blocks, 256>>>(in, out);
}